// round 17
// baseline (speedup 1.0000x reference)
#include <cuda_runtime.h>
#include <cuda_bf16.h>
#include <cuda_fp16.h>
#include <cstdint>

#define BATCH 16
#define C 256
#define D 64
#define NPIX 16384

// ---------------- device scratch (no runtime allocation) -------------------
__device__ __nv_bfloat16 g_ebf[(size_t)BATCH * D * NPIX];  // exp(logits), bf16, 32MB
__device__ float g_part[BATCH * D * 128];
__device__ float g_rowinv[BATCH * D];
__device__ __half g_W1h[4 * 64 * 72];                      // [ck][d][72] fp16, padded
__device__ float g_W2f[C * D];                             // fp32 bn-folded W2 [c][d]
__device__ __nv_bfloat16 g_W2b[BATCH * 256 * 72];          // per-batch W2*ri, bf16, padded
__device__ float g_b1[D];
__device__ float g_bias2[C];

// ---------------- helpers ---------------------------------------------------
__device__ __forceinline__ uint32_t smem_u32(const void* p) {
    uint32_t a;
    asm("{ .reg .u64 t; cvta.to.shared.u64 t, %1; cvt.u32.u64 %0, t; }" : "=r"(a) : "l"(p));
    return a;
}
__device__ __forceinline__ void ldm_x4(uint32_t addr, uint32_t* r) {
    asm volatile("ldmatrix.sync.aligned.m8n8.x4.shared.b16 {%0,%1,%2,%3}, [%4];"
        : "=r"(r[0]), "=r"(r[1]), "=r"(r[2]), "=r"(r[3]) : "r"(addr));
}
__device__ __forceinline__ void ldm_x4t(uint32_t addr, uint32_t* r) {
    asm volatile("ldmatrix.sync.aligned.m8n8.x4.trans.shared.b16 {%0,%1,%2,%3}, [%4];"
        : "=r"(r[0]), "=r"(r[1]), "=r"(r[2]), "=r"(r[3]) : "r"(addr));
}
__device__ __forceinline__ void mma_bf16(float* d, const uint32_t* a, uint32_t b0, uint32_t b1) {
    asm volatile(
        "mma.sync.aligned.m16n8k16.row.col.f32.bf16.bf16.f32 "
        "{%0,%1,%2,%3}, {%4,%5,%6,%7}, {%8,%9}, {%0,%1,%2,%3};"
        : "+f"(d[0]), "+f"(d[1]), "+f"(d[2]), "+f"(d[3])
        : "r"(a[0]), "r"(a[1]), "r"(a[2]), "r"(a[3]), "r"(b0), "r"(b1));
}
__device__ __forceinline__ void mma_f16(float* d, const uint32_t* a, uint32_t b0, uint32_t b1) {
    asm volatile(
        "mma.sync.aligned.m16n8k16.row.col.f32.f16.f16.f32 "
        "{%0,%1,%2,%3}, {%4,%5,%6,%7}, {%8,%9}, {%0,%1,%2,%3};"
        : "+f"(d[0]), "+f"(d[1]), "+f"(d[2]), "+f"(d[3])
        : "r"(a[0]), "r"(a[1]), "r"(a[2]), "r"(a[3]), "r"(b0), "r"(b1));
}
__device__ __forceinline__ void cp16(uint32_t dst, const void* src) {
    asm volatile("cp.async.ca.shared.global [%0], [%1], 16;" :: "r"(dst), "l"(src));
}
__device__ __forceinline__ void cp_commit() { asm volatile("cp.async.commit_group;"); }
__device__ __forceinline__ void cp_wait0() { asm volatile("cp.async.wait_group 0;" ::: "memory"); }

// exp via FMA-pipe polynomial (no MUFU); rel err ~2e-6
__device__ __forceinline__ float fexp(float v) {
    float t = v * 1.44269504f;
    t = fminf(fmaxf(t, -120.f), 120.f);
    float r = rintf(t);
    float f = t - r;
    float q = 0.0013333558f;
    q = fmaf(q, f, 0.0096181291f);
    q = fmaf(q, f, 0.0555041087f);
    q = fmaf(q, f, 0.2402265069f);
    q = fmaf(q, f, 0.6931471806f);
    q = fmaf(q, f, 1.0f);
    return __int_as_float(((int)r + 127) << 23) * q;
}

// ---------------------------------------------------------------------------
// K0: fold weights + BN.  W1 -> fp16 padded plane; W2 -> fp32 [c][d].
// ---------------------------------------------------------------------------
__global__ __launch_bounds__(256) void prep_kernel(
    const float* __restrict__ conv1_w, const float* __restrict__ conv1_b,
    const float* __restrict__ mk_w,    const float* __restrict__ mv_w,
    const float* __restrict__ conv2_w, const float* __restrict__ bn_gamma,
    const float* __restrict__ bn_beta, const float* __restrict__ bn_mean,
    const float* __restrict__ bn_var)
{
    int gid = blockIdx.x * blockDim.x + threadIdx.x;
    if (gid < D * C) {
        int d = gid >> 8, c = gid & 255;
        float s = 0.f;
        for (int o = 0; o < C; o++)
            s = fmaf(mk_w[d * C + o], conv1_w[o * C + c], s);
        int ck = c >> 6, cl = c & 63;
        g_W1h[ck * 4608 + d * 72 + cl] = __float2half(s);
    } else if (gid < 2 * D * C) {
        int j = gid - D * C;
        int c = j >> 6, d = j & 63;
        float inv = bn_gamma[c] * rsqrtf(bn_var[c] + 1e-5f);
        float s = 0.f;
        for (int cp = 0; cp < C; cp++)
            s = fmaf(conv2_w[c * C + cp], mv_w[cp * D + d], s);
        g_W2f[c * D + d] = s * inv;
    } else if (gid < 2 * D * C + D) {
        int d = gid - 2 * D * C;
        float s = 0.f;
        for (int o = 0; o < C; o++)
            s = fmaf(mk_w[d * C + o], conv1_b[o], s);
        g_b1[d] = s;
    } else if (gid < 2 * D * C + D + C) {
        int c = gid - 2 * D * C - D;
        float inv = bn_gamma[c] * rsqrtf(bn_var[c] + 1e-5f);
        g_bias2[c] = bn_beta[c] - bn_mean[c] * inv;
    }
}

// ---------------------------------------------------------------------------
// K1: e = exp(W1 @ x + b1) -> bf16, + per-block row partial sums.
// fp16 single-plane; DOUBLE-BUFFERED X and W, ONE sync per chunk, 4 CTAs/SM.
// ---------------------------------------------------------------------------
#define K1_X0 0                          // 17408
#define K1_X1 17408                      // 17408
#define K1_W0 34816                      // 9216
#define K1_W1 44032                      // 9216
#define K1_B1 53248                      // 256
#define K1_SPART 53504                   // 1024
#define K1_SMEM 54528

__device__ __forceinline__ void k1_stage_x(const float* __restrict__ x,
                                           char* xbuf, int b, int ck,
                                           int pix0, int w, int lane)
{
    const float* xp = x + ((size_t)b * C + ck * 64 + w * 8) * NPIX + pix0 + lane * 4;
    char* xh = xbuf + (size_t)(w * 8) * 272 + lane * 8;
#pragma unroll
    for (int jb = 0; jb < 2; jb++) {
        float4 v[4];
#pragma unroll
        for (int u = 0; u < 4; u++)
            v[u] = *(const float4*)(xp + (size_t)(jb * 4 + u) * NPIX);
#pragma unroll
        for (int u = 0; u < 4; u++) {
            int j = jb * 4 + u;
            __half2 lo2 = __floats2half2_rn(v[u].x, v[u].y);
            __half2 hi2 = __floats2half2_rn(v[u].z, v[u].w);
            uint2 pp;
            pp.x = *(uint32_t*)&lo2;
            pp.y = *(uint32_t*)&hi2;
            *(uint2*)(xh + j * 272) = pp;
        }
    }
}

__global__ __launch_bounds__(256, 4) void logits_kernel(const float* __restrict__ x)
{
    extern __shared__ char sh[];
    uint32_t sb = smem_u32(sh);
    float* b1s   = (float*)(sh + K1_B1);
    float* spart = (float*)(sh + K1_SPART);
    int tid = threadIdx.x, w = tid >> 5, lane = tid & 31;
    int b = blockIdx.y, mblk = blockIdx.x, pix0 = mblk * 128;

    if (tid < 64) b1s[tid] = g_b1[tid];

    int wm = w & 3, wq = w >> 2;
    int m0 = wm * 32, n0 = wq * 32;
    uint32_t a_k = (lane & 7) + ((lane >> 4) << 3);
    uint32_t a_mo = ((lane >> 3) & 1) * 8;
    uint32_t b_row = lane & 15;
    uint32_t b_co = (lane >> 4) << 4;

    float acc[2][4][4];
#pragma unroll
    for (int t = 0; t < 2; t++)
#pragma unroll
        for (int q = 0; q < 4; q++)
#pragma unroll
            for (int i = 0; i < 4; i++) acc[t][q][i] = 0.f;

    // prologue: W(0) cp.async + X(0) direct, into buffer 0
#pragma unroll
    for (int k = 0; k < 3; k++) {
        int idx = tid + k * 256;
        if (idx < 576) cp16(sb + K1_W0 + idx * 16, (const char*)g_W1h + idx * 16);
    }
    cp_commit();
    k1_stage_x(x, sh + K1_X0, b, 0, pix0, w, lane);
    cp_wait0();
    __syncthreads();

    for (int ck = 0; ck < 4; ck++) {
        int cur = ck & 1;
        uint32_t xb = sb + (cur ? K1_X1 : K1_X0);
        uint32_t wb = sb + (cur ? K1_W1 : K1_W0);

        // issue next W chunk async before MMA (fire-and-forget)
        if (ck < 3) {
#pragma unroll
            for (int k = 0; k < 3; k++) {
                int idx = tid + k * 256;
                if (idx < 576)
                    cp16(sb + (cur ? K1_W0 : K1_W1) + idx * 16,
                         (const char*)g_W1h + (ck + 1) * 9216 + idx * 16);
            }
            cp_commit();
        }

        // MMA on current buffers
#pragma unroll
        for (int kk = 0; kk < 4; kk++) {
            uint32_t ah[2][4];
#pragma unroll
            for (int t = 0; t < 2; t++) {
                uint32_t off = (kk * 16 + a_k) * 272 + (m0 + t * 16 + a_mo) * 2;
                ldm_x4t(xb + off, ah[t]);
            }
            uint32_t bh[2][4];
#pragma unroll
            for (int q = 0; q < 2; q++) {
                uint32_t off = (n0 + q * 16 + b_row) * 144 + kk * 32 + b_co;
                ldm_x4(wb + off, bh[q]);
            }
#pragma unroll
            for (int t = 0; t < 2; t++)
#pragma unroll
                for (int q = 0; q < 2; q++) {
                    mma_f16(acc[t][q * 2], ah[t], bh[q][0], bh[q][2]);
                    mma_f16(acc[t][q * 2 + 1], ah[t], bh[q][1], bh[q][3]);
                }
        }

        // stage next X into the other buffer (overlaps other warps' MMA)
        if (ck < 3) {
            k1_stage_x(x, sh + (cur ? K1_X0 : K1_X1), b, ck + 1, pix0, w, lane);
            cp_wait0();
        }
        __syncthreads();
    }

    // epilogue: exp -> bf16 z-tile [d][128 pix] in smem, + row partials
    __nv_bfloat16* ztb = (__nv_bfloat16*)(sh + K1_X0);
    int dbase = n0 + (lane & 3) * 2;
    int plocal = m0 + (lane >> 2);
#pragma unroll
    for (int q = 0; q < 4; q++) {
        int d0 = dbase + q * 8;
        float bb0 = b1s[d0], bb1 = b1s[d0 + 1];
        float s0 = 0.f, s1 = 0.f;
#pragma unroll
        for (int t = 0; t < 2; t++) {
            int p0 = plocal + t * 16, p1 = p0 + 8;
            float v00 = fexp(acc[t][q][0] + bb0); ztb[d0 * 128 + p0] = __float2bfloat16(v00);
            float v01 = fexp(acc[t][q][1] + bb1); ztb[(d0 + 1) * 128 + p0] = __float2bfloat16(v01);
            float v02 = fexp(acc[t][q][2] + bb0); ztb[d0 * 128 + p1] = __float2bfloat16(v02);
            float v03 = fexp(acc[t][q][3] + bb1); ztb[(d0 + 1) * 128 + p1] = __float2bfloat16(v03);
            s0 += v00 + v02; s1 += v01 + v03;
        }
        s0 += __shfl_xor_sync(0xFFFFFFFF, s0, 4);
        s0 += __shfl_xor_sync(0xFFFFFFFF, s0, 8);
        s0 += __shfl_xor_sync(0xFFFFFFFF, s0, 16);
        s1 += __shfl_xor_sync(0xFFFFFFFF, s1, 4);
        s1 += __shfl_xor_sync(0xFFFFFFFF, s1, 8);
        s1 += __shfl_xor_sync(0xFFFFFFFF, s1, 16);
        if (lane < 4) {
            spart[d0 * 4 + wm] = s0;
            spart[(d0 + 1) * 4 + wm] = s1;
        }
    }
    __syncthreads();
    if (tid < 64) {
        float s = spart[tid * 4] + spart[tid * 4 + 1] + spart[tid * 4 + 2] + spart[tid * 4 + 3];
        g_part[(b * D + tid) * 128 + mblk] = s;
    }
    // coalesced bf16 store: 1024 x 16B items
#pragma unroll
    for (int k = 0; k < 4; k++) {
        int idx = tid + k * 256;
        int row = idx >> 4, ch = idx & 15;
        uint4 v = *(uint4*)((char*)ztb + row * 256 + ch * 16);
        *(uint4*)((char*)g_ebf + ((size_t)(b * D + row) * NPIX + pix0) * 2 + ch * 16) = v;
    }
}

// ---------------------------------------------------------------------------
// K2: rowinv + per-batch W2' = W2 * ri[d] -> single bf16 plane, padded.
// ---------------------------------------------------------------------------
__global__ __launch_bounds__(256) void rowinv_kernel()
{
    __shared__ float ri_s[64];
    __shared__ float red[256];
    int b = blockIdx.x, tid = threadIdx.x;
    int r = tid >> 2, qq = tid & 3;
    float s = 0.f;
#pragma unroll
    for (int i = 0; i < 32; i++)
        s += g_part[(b * D + r) * 128 + qq * 32 + i];
    red[tid] = s;
    __syncthreads();
    if (qq == 0) {
        float t = red[tid] + red[tid + 1] + red[tid + 2] + red[tid + 3];
        float ri = 1.f / t;
        ri_s[r] = ri;
        g_rowinv[b * D + r] = ri;
    }
    __syncthreads();
#pragma unroll
    for (int k = 0; k < 64; k++) {
        int idx = tid + k * 256;
        int c = idx >> 6, d = idx & 63;
        float wv = g_W2f[idx] * ri_s[d];
        g_W2b[(size_t)b * 18432 + c * 72 + d] = __float2bfloat16(wv);
    }
}

// ---------------------------------------------------------------------------
// K3: out = relu(W2' @ e * scale + bias2 + x); scale = 1/(1e-9 + colsum(ri*e)).
// Single-plane bf16 W2' (half the MMAs of R16).  128 pix x 64 c, 4 CTAs/SM.
// zt epilogue tile needs [0,32768) -> RI/B2/CS/SC placed above 32768.
// ---------------------------------------------------------------------------
#define K3_A  0                          // 17408
#define K3_W  17408                      // 9216
#define K3_RI 32768                      // 256
#define K3_B2 33024                      // 256
#define K3_CS 33280                      // 2048
#define K3_SC 35328                      // 512
#define K3_SMEM 35840

__global__ __launch_bounds__(256, 4) void output_kernel(const float* __restrict__ x,
                                                        float* __restrict__ out)
{
    extern __shared__ char sh[];
    uint32_t sb = smem_u32(sh);
    float* ri_s = (float*)(sh + K3_RI);
    float* b2_s = (float*)(sh + K3_B2);
    float* cs   = (float*)(sh + K3_CS);
    float* sc_s = (float*)(sh + K3_SC);
    int tid = threadIdx.x, w = tid >> 5, lane = tid & 31;
    int b = blockIdx.y;
    int cblk = blockIdx.x & 3, pixblk = blockIdx.x >> 2;
    int pix0 = pixblk * 128, cb0 = cblk * 64;

#pragma unroll
    for (int k = 0; k < 4; k++) {
        int idx = tid + k * 256;
        int d = idx >> 4, ch = idx & 15;
        cp16(sb + K3_A + d * 272 + ch * 16,
             (const char*)g_ebf + ((size_t)(b * D + d) * NPIX + pix0) * 2 + ch * 16);
    }
#pragma unroll
    for (int k = 0; k < 3; k++) {
        int idx = tid + k * 256;
        if (idx < 576)
            cp16(sb + K3_W + idx * 16,
                 (const char*)g_W2b + (size_t)b * 36864 + cb0 * 144 + idx * 16);
    }
    cp_commit();
    if (tid < 64) {
        ri_s[tid] = g_rowinv[b * D + tid];
        b2_s[tid] = g_bias2[cb0 + tid];
    }
    cp_wait0();
    __syncthreads();

    // colsum over d of ri*e -> per-pixel scale (bf16x2 vectorized)
    {
        int pair = tid & 63;
        int dg = tid >> 6;
        float s0 = 0.f, s1 = 0.f;
#pragma unroll
        for (int j = 0; j < 16; j++) {
            int d = dg * 16 + j;
            __nv_bfloat162 e2 = *(const __nv_bfloat162*)(sh + K3_A + d * 272 + pair * 4);
            float ri = ri_s[d];
            s0 = fmaf(__bfloat162float(e2.x), ri, s0);
            s1 = fmaf(__bfloat162float(e2.y), ri, s1);
        }
        cs[dg * 128 + pair * 2]     = s0;
        cs[dg * 128 + pair * 2 + 1] = s1;
    }
    __syncthreads();
    if (tid < 128)
        sc_s[tid] = 1.f / (1e-9f + cs[tid] + cs[128 + tid] + cs[256 + tid] + cs[384 + tid]);
    __syncthreads();

    int wm = w & 3, wq = w >> 2;
    int m0 = wm * 32, n0 = wq * 32;
    uint32_t a_k = (lane & 7) + ((lane >> 4) << 3);
    uint32_t a_mo = ((lane >> 3) & 1) * 8;
    uint32_t b_row = lane & 15;
    uint32_t b_co = (lane >> 4) << 4;

    float acc[2][4][4];
#pragma unroll
    for (int t = 0; t < 2; t++)
#pragma unroll
        for (int q = 0; q < 4; q++)
#pragma unroll
            for (int i = 0; i < 4; i++) acc[t][q][i] = 0.f;

#pragma unroll
    for (int kk = 0; kk < 4; kk++) {
        uint32_t ah[2][4];
#pragma unroll
        for (int t = 0; t < 2; t++) {
            uint32_t off = (kk * 16 + a_k) * 272 + (m0 + t * 16 + a_mo) * 2;
            ldm_x4t(sb + K3_A + off, ah[t]);
        }
#pragma unroll
        for (int q = 0; q < 2; q++) {
            uint32_t off = (n0 + q * 16 + b_row) * 144 + kk * 32 + b_co;
            uint32_t bh[4];
            ldm_x4(sb + K3_W + off, bh);
#pragma unroll
            for (int t = 0; t < 2; t++) {
                mma_bf16(acc[t][q * 2], ah[t], bh[0], bh[2]);
                mma_bf16(acc[t][q * 2 + 1], ah[t], bh[1], bh[3]);
            }
        }
    }

    __syncthreads();
    float* zt = (float*)sh;
    {
        int clb = n0 + (lane & 3) * 2;
        int plocal = m0 + (lane >> 2);
#pragma unroll
        for (int t = 0; t < 2; t++) {
            int p0 = plocal + t * 16, p1 = p0 + 8;
#pragma unroll
            for (int q = 0; q < 4; q++) {
                int cl = clb + q * 8;
                zt[cl * 128 + p0]       = acc[t][q][0];
                zt[(cl + 1) * 128 + p0] = acc[t][q][1];
                zt[cl * 128 + p1]       = acc[t][q][2];
                zt[(cl + 1) * 128 + p1] = acc[t][q][3];
            }
        }
    }
    __syncthreads();

#pragma unroll
    for (int k = 0; k < 8; k++) {
        int idx = tid + k * 256;
        int row = idx >> 5, col = idx & 31;
        float4 z4 = ((const float4*)zt)[row * 32 + col];
        float4 sc4 = *(const float4*)(sc_s + col * 4);
        float bb = b2_s[row];
        size_t go = ((size_t)(b * C + cb0 + row)) * NPIX + pix0 + col * 4;
        float4 x4 = *(const float4*)(x + go);
        float4 o;
        o.x = fmaxf(fmaf(z4.x, sc4.x, bb) + x4.x, 0.f);
        o.y = fmaxf(fmaf(z4.y, sc4.y, bb) + x4.y, 0.f);
        o.z = fmaxf(fmaf(z4.z, sc4.z, bb) + x4.z, 0.f);
        o.w = fmaxf(fmaf(z4.w, sc4.w, bb) + x4.w, 0.f);
        *(float4*)(out + go) = o;
    }
}

// ---------------------------------------------------------------------------
extern "C" void kernel_launch(void* const* d_in, const int* in_sizes, int n_in,
                              void* d_out, int out_size)
{
    const float* x       = (const float*)d_in[0];
    const float* conv1_w = (const float*)d_in[1];
    const float* conv1_b = (const float*)d_in[2];
    const float* mk_w    = (const float*)d_in[3];
    const float* mv_w    = (const float*)d_in[4];
    const float* conv2_w = (const float*)d_in[5];
    const float* gamma   = (const float*)d_in[6];
    const float* beta    = (const float*)d_in[7];
    const float* mean    = (const float*)d_in[8];
    const float* var     = (const float*)d_in[9];
    float* out = (float*)d_out;

    cudaFuncSetAttribute(logits_kernel, cudaFuncAttributeMaxDynamicSharedMemorySize, K1_SMEM);
    cudaFuncSetAttribute(output_kernel, cudaFuncAttributeMaxDynamicSharedMemorySize, K3_SMEM);

    prep_kernel<<<130, 256>>>(conv1_w, conv1_b, mk_w, mv_w, conv2_w,
                              gamma, beta, mean, var);

    dim3 g1(NPIX / 128, BATCH);
    logits_kernel<<<g1, 256, K1_SMEM>>>(x);

    rowinv_kernel<<<BATCH, 256>>>();

    dim3 g3((NPIX / 128) * 4, BATCH);
    output_kernel<<<g3, 256, K3_SMEM>>>(x, out);
}